// round 7
// baseline (speedup 1.0000x reference)
#include <cuda_runtime.h>
#include <math.h>

// Problem constants (fixed shapes from reference)
#define VSZ 50000
#define DIM 300
#define DP  304      // padded dim (zero-filled 300..303)
#define BB  256
#define QQ  16
#define TT_TOT 1024
#define KK  11
#define TTILE 256    // tokens per block
#define NSPLIT 4     // blocks per (b,side)
#define CH  8        // dims per smem chunk (double-buffered)
#define NCH (DP/CH)  // 38
#define DTSTRIDE 260 // words; bank = (4*gd + tb) mod 32 -> conflict-free gather STS

// Packed fp32x2 FMA (sm_103a; component-wise, rounding identical to fmaf)
#define FMA2(acc, a, b)  asm("fma.rn.f32x2 %0, %1, %2, %0;" : "+l"(acc) : "l"(a), "l"(b))
#define UNPK2(lo, hi, v) asm("mov.b64 {%0, %1}, %2;" : "=f"(lo), "=f"(hi) : "l"(v))

typedef unsigned long long u64;

// Pre-normalized embedding table (~61.9 MB scratch; static __device__ allowed)
__device__ float g_embn[(size_t)VSZ * DP];
// Per-block partials: [2048][16][12]  (q-major; [q][0..10]=doc_k, [q][11]=sim-sum)
__device__ float g_part[(size_t)BB * 2 * NSPLIT * QQ * 12];
// Completion counters per (b,side) pair; reset by normalize kernel each run
__device__ int g_count[BB * 2];

// Dynamic smem layout (float offsets)
#define QT2_OFF   0                     // [DP][32]   duplicated queries (9728 f)
#define DT_OFF    (QT2_OFF + DP * 32)   // [2][CH*DTSTRIDE] ping-pong doc tiles (4160 f)
#define SDM_OFF   (DT_OFF + 2 * CH * DTSTRIDE) // [256] doc pad mask
#define STOK_OFF  (SDM_OFF + TTILE)     // [256] token ids (as int)
#define SQM_OFF   (STOK_OFF + TTILE)    // [16]
#define SWARP_OFF (SQM_OFF + QQ)        // [8][4][12]
#define SMU_OFF   (SWARP_OFF + 8 * 4 * 12)
#define SC2_OFF   (SMU_OFF + KK)
#define SFLAG_OFF (SC2_OFF + KK)        // int flag
#define SMEM_FLOATS (SFLAG_OFF + 2)
#define SMEM_BYTES  (SMEM_FLOATS * 4 + 128)

// ---------------------------------------------------------------------------
// Kernel 1: normalize emb rows into g_embn (padded); also reset g_count.
// ---------------------------------------------------------------------------
__global__ __launch_bounds__(256) void normalize_emb_kernel(const float* __restrict__ emb) {
    if (blockIdx.x == 0) {
        for (int i = threadIdx.x; i < BB * 2; i += 256) g_count[i] = 0;
    }
    int row  = blockIdx.x * 8 + (threadIdx.x >> 5);
    int lane = threadIdx.x & 31;
    if (row >= VSZ) return;
    const float* src = emb + (size_t)row * DIM;
    float v[10];
    float ssq = 0.f;
#pragma unroll
    for (int j = 0; j < 10; j++) {
        int d = lane + 32 * j;
        v[j] = (d < DIM) ? src[d] : 0.f;
        ssq += v[j] * v[j];
    }
#pragma unroll
    for (int off = 16; off; off >>= 1) ssq += __shfl_xor_sync(0xffffffffu, ssq, off);
    float scale = 1.f / (sqrtf(ssq) + 1e-9f);
    float* dst = g_embn + (size_t)row * DP;
#pragma unroll
    for (int j = 0; j < 10; j++) {
        int d = lane + 32 * j;
        if (d < DP) dst[d] = (d < DIM) ? v[j] * scale : 0.f;
    }
}

// Per-dim compute: 2 broadcast LDS.128 (dup'd q pairs) + 2 LDS.64 (packed token
// pairs) + 8 FFMA2 = 12 issue slots for 16 lane-MACs.
#define COMPUTE_CHUNK(db, cbase)                                                   \
    _Pragma("unroll")                                                              \
    for (int d = 0; d < CH; d++) {                                                 \
        const float* qrow = &smf[QT2_OFF + (cbase + d) * 32 + 8 * qg];             \
        const ulonglong2 qA = *(const ulonglong2*)qrow;        /* (q0q0,q1q1) */   \
        const ulonglong2 qB = *(const ulonglong2*)(qrow + 4);  /* (q2q2,q3q3) */   \
        const u64 d0 = *(const u64*)&(db)[d * DTSTRIDE + 2 * u];                   \
        const u64 d1 = *(const u64*)&(db)[d * DTSTRIDE + 128 + 2 * u];             \
        FMA2(acc2[0][0], qA.x, d0); FMA2(acc2[0][1], qA.x, d1);                    \
        FMA2(acc2[1][0], qA.y, d0); FMA2(acc2[1][1], qA.y, d1);                    \
        FMA2(acc2[2][0], qB.x, d0); FMA2(acc2[2][1], qB.x, d1);                    \
        FMA2(acc2[3][0], qB.y, d0); FMA2(acc2[3][1], qB.y, d1);                    \
    }

// ---------------------------------------------------------------------------
// Kernel 2: one block per (b, side, tile). 256 threads. Fused finalize.
// Thread tile: 4 q x token pairs {(2u,2u+1),(128+2u,128+2u+1)}, u = tid&63.
// Distance-2 prefetch through a double-buffered smem tile.
// ---------------------------------------------------------------------------
__global__ __launch_bounds__(256, 3) void knrm_main_kernel(
    const int* __restrict__ posdoc, const int* __restrict__ negdoc,
    const int* __restrict__ query,
    const float* __restrict__ mus, const float* __restrict__ sigmas,
    const float* __restrict__ W, const float* __restrict__ bvec,
    float* __restrict__ out)
{
    extern __shared__ __align__(16) float smf[];
    int* smi = (int*)smf;

    const int tid   = threadIdx.x;
    const int bx    = blockIdx.x;
    const int tile  = bx & (NSPLIT - 1);
    const int pairI = bx >> 2;              // b*2+side
    const int b     = pairI >> 1;
    const int side  = pairI & 1;
    const int* doc  = (side ? negdoc : posdoc) + b * TT_TOT + tile * TTILE;
    const int* qtok = query + b * QQ;

    if (tid < KK) {
        float s = sigmas[tid];
        smf[SMU_OFF + tid] = mus[tid];
        smf[SC2_OFF + tid] = -0.5f / (s * s);
    }
    if (tid < QQ) smf[SQM_OFF + tid] = (qtok[tid] != 0) ? 1.f : 0.f;

    // Doc tokens + pad mask for this block's 256 tokens
    {
        int tk = doc[tid];
        smi[STOK_OFF + tid] = tk;
        smf[SDM_OFF + tid]  = (tk != 0) ? 1.f : 0.f;
    }

    // Duplicated transposed query tile: qt2[d][2q]=qt2[d][2q+1]=qn[q][d]
#pragma unroll 1
    for (int q = 0; q < QQ; q++) {
        const float* src = g_embn + (size_t)qtok[q] * DP;
        for (int d = tid; d < DP; d += 256) {
            float v = src[d];
            smf[QT2_OFF + d * 32 + 2 * q]     = v;
            smf[QT2_OFF + d * 32 + 2 * q + 1] = v;
        }
    }
    __syncthreads();

    // Gather-role indices: lane gd in 0..7 loads dim ch*8+gd of 8 tokens
    const int gd = tid & 7;
    const int tb = tid >> 3;            // 0..31
    int toks[CH];
#pragma unroll
    for (int r = 0; r < CH; r++) toks[r] = smi[STOK_OFF + tb + 32 * r];

    // Compute-role indices
    const int qg = tid >> 6;            // q group (0..3), constant per warp
    const int u  = tid & 63;

    // Packed accumulators: acc2[j][p] = (sim[qj][tok 2p-pair lo], sim[qj][hi])
    u64 acc2[4][2];
#pragma unroll
    for (int j = 0; j < 4; j++) { acc2[j][0] = 0ull; acc2[j][1] = 0ull; }

    float* dt0 = &smf[DT_OFF];
    float* dt1 = &smf[DT_OFF + CH * DTSTRIDE];

    // Pipeline prologue: chunks 0 and 1 in flight
    float gA[CH], gB[CH];
#pragma unroll
    for (int r = 0; r < CH; r++) gA[r] = g_embn[(size_t)toks[r] * DP + gd];
#pragma unroll
    for (int r = 0; r < CH; r++) gB[r] = g_embn[(size_t)toks[r] * DP + CH + gd];

#pragma unroll 1
    for (int ch = 0; ch < NCH; ch += 2) {
        // chunk ch from gA -> dt0
#pragma unroll
        for (int r = 0; r < CH; r++) dt0[gd * DTSTRIDE + tb + 32 * r] = gA[r];
        __syncthreads();
        if (ch + 2 < NCH) {
            const size_t cb = (size_t)((ch + 2) * CH + gd);
#pragma unroll
            for (int r = 0; r < CH; r++) gA[r] = g_embn[(size_t)toks[r] * DP + cb];
        }
        COMPUTE_CHUNK(dt0, ch * CH)

        // chunk ch+1 from gB -> dt1
#pragma unroll
        for (int r = 0; r < CH; r++) dt1[gd * DTSTRIDE + tb + 32 * r] = gB[r];
        __syncthreads();
        if (ch + 3 < NCH) {
            const size_t cb = (size_t)((ch + 3) * CH + gd);
#pragma unroll
            for (int r = 0; r < CH; r++) gB[r] = g_embn[(size_t)toks[r] * DP + cb];
        }
        COMPUTE_CHUNK(dt1, (ch + 1) * CH)
    }

    // Unpack packed accumulators: accf[j][i], tokens {2u,2u+1,128+2u,128+2u+1}
    float accf[4][4];
#pragma unroll
    for (int j = 0; j < 4; j++) {
        UNPK2(accf[j][0], accf[j][1], acc2[j][0]);
        UNPK2(accf[j][2], accf[j][3], acc2[j][1]);
    }

    // RBF kernel bank + accumulation (masked pairs contribute k(0), matching ref)
    float dock[4][KK];
    float ssm[4];
    {
        const float2 dma = *(const float2*)&smf[SDM_OFF + 2 * u];
        const float2 dmb = *(const float2*)&smf[SDM_OFF + 128 + 2 * u];
        const float dmv[4] = {dma.x, dma.y, dmb.x, dmb.y};
#pragma unroll
        for (int j = 0; j < 4; j++) {
            ssm[j] = 0.f;
#pragma unroll
            for (int k = 0; k < KK; k++) dock[j][k] = 0.f;
            const float qm = smf[SQM_OFF + qg * 4 + j];
#pragma unroll
            for (int i = 0; i < 4; i++) {
                float s = accf[j][i] * qm * dmv[i];
                ssm[j] += s;
#pragma unroll
                for (int k = 0; k < KK; k++) {
                    float df = s - smf[SMU_OFF + k];
                    dock[j][k] += __expf(df * df * smf[SC2_OFF + k]);
                }
            }
        }
    }

    // Warp butterfly reduce (all lanes of a warp share qg) -> per-warp slots
#pragma unroll
    for (int j = 0; j < 4; j++) {
#pragma unroll
        for (int off = 16; off; off >>= 1) ssm[j] += __shfl_xor_sync(0xffffffffu, ssm[j], off);
#pragma unroll
        for (int k = 0; k < KK; k++) {
#pragma unroll
            for (int off = 16; off; off >>= 1) dock[j][k] += __shfl_xor_sync(0xffffffffu, dock[j][k], off);
        }
    }
    const int wid = tid >> 5;
    if ((tid & 31) == 0) {
#pragma unroll
        for (int j = 0; j < 4; j++) {
            smf[SWARP_OFF + wid * 48 + j * 12 + 11] = ssm[j];
#pragma unroll
            for (int k = 0; k < KK; k++) smf[SWARP_OFF + wid * 48 + j * 12 + k] = dock[j][k];
        }
    }
    __syncthreads();

    // Fixed-order combine of the two warps owning each q group -> global partials
    if (tid < QQ * 12) {
        const int q  = tid / 12;
        const int kk = tid - q * 12;
        const int w0 = (q >> 2) * 2;     // q group g is owned by warps 2g, 2g+1
        const int j  = q & 3;
        g_part[(size_t)bx * (QQ * 12) + tid] =
            smf[SWARP_OFF + w0 * 48 + j * 12 + kk] + smf[SWARP_OFF + (w0 + 1) * 48 + j * 12 + kk];
    }

    // Last block of this pair finalizes (values deterministic; order fixed)
    __threadfence();
    __syncthreads();
    if (tid == 0) {
        int old = atomicAdd(&g_count[pairI], 1);
        smi[SFLAG_OFF] = (old == NSPLIT - 1);
    }
    __syncthreads();
    if (smi[SFLAG_OFF] && tid < 32) {
        const float* base = g_part + (size_t)pairI * NSPLIT * QQ * 12;
        float part = 0.f;
        if (tid < KK) {
#pragma unroll 1
            for (int q = 0; q < QQ; q++) {
                float dk = 0.f, ss = 0.f;
#pragma unroll
                for (int s = 0; s < NSPLIT; s++) {
                    dk += __ldcg(&base[s * QQ * 12 + q * 12 + tid]);
                    ss += __ldcg(&base[s * QQ * 12 + q * 12 + 11]);
                }
                if (ss != 0.f) part += logf(dk + 1e-6f);
            }
            part *= W[tid];
        }
#pragma unroll
        for (int off = 16; off; off >>= 1) part += __shfl_xor_sync(0xffffffffu, part, off);
        if (tid == 0) out[pairI] = part + bvec[0];
    }
}

// ---------------------------------------------------------------------------
// Launch. Inputs (metadata order): posdoc, negdoc, query, query_idf, emb,
// mus, sigmas, W, b. Output: [B,2] float.
// ---------------------------------------------------------------------------
extern "C" void kernel_launch(void* const* d_in, const int* in_sizes, int n_in,
                              void* d_out, int out_size) {
    const int*   posdoc = (const int*)d_in[0];
    const int*   negdoc = (const int*)d_in[1];
    const int*   query  = (const int*)d_in[2];
    // d_in[3] = query_idf (unused by the reference computation)
    const float* emb    = (const float*)d_in[4];
    const float* mus    = (const float*)d_in[5];
    const float* sigmas = (const float*)d_in[6];
    const float* W      = (const float*)d_in[7];
    const float* bvec   = (const float*)d_in[8];
    float* out = (float*)d_out;

    // Unconditional (no static guards per harness rules); these are not stream
    // ops, are not captured into the graph, and the attributes are sticky.
    cudaFuncSetAttribute(knrm_main_kernel,
                         cudaFuncAttributeMaxDynamicSharedMemorySize, SMEM_BYTES);
    cudaFuncSetAttribute(knrm_main_kernel,
                         cudaFuncAttributePreferredSharedMemoryCarveout, 100);

    normalize_emb_kernel<<<(VSZ + 7) / 8, 256>>>(emb);
    knrm_main_kernel<<<BB * 2 * NSPLIT, 256, SMEM_BYTES>>>(
        posdoc, negdoc, query, mus, sigmas, W, bvec, out);
}

// round 14
// speedup vs baseline: 1.2610x; 1.2610x over previous
#include <cuda_runtime.h>
#include <math.h>

// Problem constants (fixed shapes from reference)
#define VSZ 50000
#define DIM 300
#define DP  304      // padded dim (zero-filled 300..303); 304 = 19*16
#define BB  256
#define QQ  16
#define TT_TOT 1024
#define KK  11
#define TTILE 256    // tokens per block
#define NSPLIT 4     // blocks per (b,side)
#define NCHK 19      // chunks of 16 dims
#define DPC  8       // dim-pairs per chunk
#define DPAIRS (DP/2)        // 152
#define DTSU 258     // dt row stride in u64 (258 mod 16 = 2 -> conflict-free STS.64)
#define DTBUFU (DPC * DTSU)  // 2064 u64 per buffer

// Packed fp32x2 FMA (sm_103a; component-wise, rounding identical to fmaf)
#define FMA2(acc, a, b)  asm("fma.rn.f32x2 %0, %1, %2, %0;" : "+l"(acc) : "l"(a), "l"(b))
#define UNPK2(lo, hi, v) asm("mov.b64 {%0, %1}, %2;" : "=f"(lo), "=f"(hi) : "l"(v))

typedef unsigned long long u64;

// Pre-normalized embedding table (~61.9 MB scratch; static __device__ allowed)
__device__ float g_embn[(size_t)VSZ * DP];
// Per-block partials: [2048][16][12]  (q-major; [q][0..10]=doc_k, [q][11]=sim-sum)
__device__ float g_part[(size_t)BB * 2 * NSPLIT * QQ * 12];
// Completion counters per (b,side) pair; reset by normalize kernel each run
__device__ int g_count[BB * 2];

// Dynamic smem layout (float offsets)
#define QTP_OFF   0                               // [152][16] u64 q dim-pairs (4864 f)
#define DT_OFF    (QTP_OFF + DPAIRS * QQ * 2)     // 2 ping-pong buffers (8256 f)
#define SDM_OFF   (DT_OFF + 2 * DTBUFU * 2)       // [256] doc pad mask
#define STOK_OFF  (SDM_OFF + TTILE)               // [256] token ids (as int)
#define SQM_OFF   (STOK_OFF + TTILE)              // [16]
#define SWQ_OFF   (SQM_OFF + QQ)                  // [8 warps][8 q][12]
#define SMU_OFF   (SWQ_OFF + 8 * 8 * 12)
#define SC2_OFF   (SMU_OFF + KK)
#define SFLAG_OFF (SC2_OFF + KK)
#define SMEM_FLOATS (SFLAG_OFF + 2)
#define SMEM_BYTES  (SMEM_FLOATS * 4 + 16)

// ---------------------------------------------------------------------------
// Kernel 1: normalize emb rows into g_embn (padded); also reset g_count.
// ---------------------------------------------------------------------------
__global__ __launch_bounds__(256) void normalize_emb_kernel(const float* __restrict__ emb) {
    if (blockIdx.x == 0) {
        for (int i = threadIdx.x; i < BB * 2; i += 256) g_count[i] = 0;
    }
    int row  = blockIdx.x * 8 + (threadIdx.x >> 5);
    int lane = threadIdx.x & 31;
    if (row >= VSZ) return;
    const float* src = emb + (size_t)row * DIM;
    float v[10];
    float ssq = 0.f;
#pragma unroll
    for (int j = 0; j < 10; j++) {
        int d = lane + 32 * j;
        v[j] = (d < DIM) ? src[d] : 0.f;
        ssq += v[j] * v[j];
    }
#pragma unroll
    for (int off = 16; off; off >>= 1) ssq += __shfl_xor_sync(0xffffffffu, ssq, off);
    float scale = 1.f / (sqrtf(ssq) + 1e-9f);
    float* dst = g_embn + (size_t)row * DP;
#pragma unroll
    for (int j = 0; j < 10; j++) {
        int d = lane + 32 * j;
        if (d < DP) dst[d] = (d < DIM) ? v[j] * scale : 0.f;
    }
}

// ---------------------------------------------------------------------------
// Kernel 2: one block per (b, side, tile). 256 threads. Fused finalize.
// Compute tile: 8 q x 2 tokens per thread (2 q-groups -> doc redundancy 2).
// FMA2 packs dim pairs. Gather: LDG.64 (token dim-pair, 64B-dense) staged in
// regs, STS.64 conflict-free, ping-pong buffers, 1 barrier per chunk.
// ---------------------------------------------------------------------------
__global__ __launch_bounds__(256, 3) void knrm_main_kernel(
    const int* __restrict__ posdoc, const int* __restrict__ negdoc,
    const int* __restrict__ query,
    const float* __restrict__ mus, const float* __restrict__ sigmas,
    const float* __restrict__ W, const float* __restrict__ bvec,
    float* __restrict__ out)
{
    extern __shared__ __align__(16) float smf[];
    int* smi = (int*)smf;
    u64* qtp = (u64*)(smf + QTP_OFF);
    u64* dtu = (u64*)(smf + DT_OFF);

    const int tid   = threadIdx.x;
    const int bx    = blockIdx.x;
    const int tile  = bx & (NSPLIT - 1);
    const int pairI = bx >> 2;              // b*2+side
    const int b     = pairI >> 1;
    const int side  = pairI & 1;
    const int* doc  = (side ? negdoc : posdoc) + b * TT_TOT + tile * TTILE;
    const int* qtok = query + b * QQ;

    if (tid < KK) {
        float s = sigmas[tid];
        smf[SMU_OFF + tid] = mus[tid];
        smf[SC2_OFF + tid] = -0.5f / (s * s);
    }
    if (tid < QQ) smf[SQM_OFF + tid] = (qtok[tid] != 0) ? 1.f : 0.f;

    // Doc tokens + pad mask
    {
        int tk = doc[tid];
        smi[STOK_OFF + tid] = tk;
        smf[SDM_OFF + tid]  = (tk != 0) ? 1.f : 0.f;
    }

    // Query dim-pair tile: qtp[dp*16 + q] = (qn[q][2dp], qn[q][2dp+1])
#pragma unroll 1
    for (int q = 0; q < QQ; q++) {
        const float* src = g_embn + (size_t)qtok[q] * DP;
        for (int d = tid; d < DP; d += 256)
            smf[QTP_OFF + ((d >> 1) * QQ + q) * 2 + (d & 1)] = src[d];
    }
    __syncthreads();

    // Gather role: lane = (dpg in 0..7, tg in 0..3); LDG r covers token
    // 32w + 4r + tg, dims [16ch + 2dpg, +1] as one float2 (64B-dense per warp).
    const int w   = tid >> 5;
    const int ln  = tid & 31;
    const int dpg = ln & 7;
    const int tg  = ln >> 3;
    int off[8];                 // float index of (token row + 2dpg), chunk 0
#pragma unroll
    for (int r = 0; r < 8; r++)
        off[r] = smi[STOK_OFF + 32 * w + 4 * r + tg] * DP + 2 * dpg;
    // STS.64 target: u64 idx dpg*258 + token  (bank16 = 2dpg+tg+4r: conflict-free)
    u64* stsb = dtu + dpg * DTSU + 32 * w + tg;

    // Compute role: q-group qg (0..1) -> q 8qg..8qg+7; tokens 2v, 2v+1
    const int qg = tid >> 7;
    const int v  = tid & 127;

    // Dim-packed accumulators: acc2[j][t] for q=8qg+j, tokens {2v,2v+1}
    u64 acc2[8][2];
#pragma unroll
    for (int j = 0; j < 8; j++) { acc2[j][0] = 0ull; acc2[j][1] = 0ull; }

    // Prologue: stage chunk 0 in registers
    float2 g[8];
#pragma unroll
    for (int r = 0; r < 8; r++) g[r] = *(const float2*)&g_embn[off[r]];

#pragma unroll 1
    for (int ch = 0; ch < NCHK; ch++) {
        u64* dbu = dtu + (ch & 1) * DTBUFU;
        // Drain register stage into this chunk's buffer (conflict-free STS.64)
        {
            u64* s = stsb + (ch & 1) * DTBUFU;
#pragma unroll
            for (int r = 0; r < 8; r++) *(float2*)&s[4 * r] = g[r];
        }
        __syncthreads();
        // Stage next chunk; LDGs fly under the FFMA2 block below
        if (ch + 1 < NCHK) {
            const int cb = (ch + 1) * 16;
#pragma unroll
            for (int r = 0; r < 8; r++) g[r] = *(const float2*)&g_embn[off[r] + cb];
        }
#pragma unroll
        for (int dp = 0; dp < DPC; dp++) {
            const u64* qp = qtp + (ch * DPC + dp) * QQ + 8 * qg;
            const ulonglong2 q01 = *(const ulonglong2*)qp;        // broadcast
            const ulonglong2 q23 = *(const ulonglong2*)(qp + 2);
            const ulonglong2 q45 = *(const ulonglong2*)(qp + 4);
            const ulonglong2 q67 = *(const ulonglong2*)(qp + 6);
            const ulonglong2 dk  = *(const ulonglong2*)&dbu[dp * DTSU + 2 * v]; // tokens 2v,2v+1
            FMA2(acc2[0][0], q01.x, dk.x); FMA2(acc2[0][1], q01.x, dk.y);
            FMA2(acc2[1][0], q01.y, dk.x); FMA2(acc2[1][1], q01.y, dk.y);
            FMA2(acc2[2][0], q23.x, dk.x); FMA2(acc2[2][1], q23.x, dk.y);
            FMA2(acc2[3][0], q23.y, dk.x); FMA2(acc2[3][1], q23.y, dk.y);
            FMA2(acc2[4][0], q45.x, dk.x); FMA2(acc2[4][1], q45.x, dk.y);
            FMA2(acc2[5][0], q45.y, dk.x); FMA2(acc2[5][1], q45.y, dk.y);
            FMA2(acc2[6][0], q67.x, dk.x); FMA2(acc2[6][1], q67.x, dk.y);
            FMA2(acc2[7][0], q67.y, dk.x); FMA2(acc2[7][1], q67.y, dk.y);
        }
        // single barrier per chunk: next STS targets the other buffer
    }

    // RBF bank, processed sequentially per q (11 live dock regs only).
    // Masked pairs contribute k(0), matching the reference.
    {
        const float dm0 = smf[SDM_OFF + 2 * v];
        const float dm1 = smf[SDM_OFF + 2 * v + 1];
#pragma unroll
        for (int j = 0; j < 8; j++) {
            const float qm = smf[SQM_OFF + 8 * qg + j];
            float lo, hi;
            UNPK2(lo, hi, acc2[j][0]); float s0 = (lo + hi) * qm * dm0;
            UNPK2(lo, hi, acc2[j][1]); float s1 = (lo + hi) * qm * dm1;
            float red[12];
            red[11] = s0 + s1;
#pragma unroll
            for (int k = 0; k < KK; k++) {
                float c2 = smf[SC2_OFF + k], mu = smf[SMU_OFF + k];
                float d0 = s0 - mu, d1 = s1 - mu;
                red[k] = __expf(d0 * d0 * c2) + __expf(d1 * d1 * c2);
            }
#pragma unroll
            for (int k = 0; k < 12; k++) {
#pragma unroll
                for (int o = 16; o; o >>= 1) red[k] += __shfl_xor_sync(0xffffffffu, red[k], o);
            }
            if (ln == 0) {
#pragma unroll
                for (int k = 0; k < 12; k++) smf[SWQ_OFF + (w * 8 + j) * 12 + k] = red[k];
            }
        }
    }
    __syncthreads();

    // Fixed-order combine: q-group g owned by warps 4g..4g+3 -> global partials
    if (tid < QQ * 12) {
        const int q  = tid / 12;
        const int kk = tid - q * 12;
        const int j  = q & 7;
        const int w0 = (q >> 3) * 4;
        float sum = smf[SWQ_OFF + ((w0 + 0) * 8 + j) * 12 + kk]
                  + smf[SWQ_OFF + ((w0 + 1) * 8 + j) * 12 + kk]
                  + smf[SWQ_OFF + ((w0 + 2) * 8 + j) * 12 + kk]
                  + smf[SWQ_OFF + ((w0 + 3) * 8 + j) * 12 + kk];
        g_part[(size_t)bx * (QQ * 12) + tid] = sum;
    }

    // Last block of this pair finalizes (values deterministic; order fixed)
    __threadfence();
    __syncthreads();
    if (tid == 0) {
        int old = atomicAdd(&g_count[pairI], 1);
        smi[SFLAG_OFF] = (old == NSPLIT - 1);
    }
    __syncthreads();
    if (smi[SFLAG_OFF] && tid < 32) {
        const float* base = g_part + (size_t)pairI * NSPLIT * QQ * 12;
        float part = 0.f;
        if (tid < KK) {
#pragma unroll 1
            for (int q = 0; q < QQ; q++) {
                float dk = 0.f, ss = 0.f;
#pragma unroll
                for (int s = 0; s < NSPLIT; s++) {
                    dk += __ldcg(&base[s * QQ * 12 + q * 12 + tid]);
                    ss += __ldcg(&base[s * QQ * 12 + q * 12 + 11]);
                }
                if (ss != 0.f) part += logf(dk + 1e-6f);
            }
            part *= W[tid];
        }
#pragma unroll
        for (int o = 16; o; o >>= 1) part += __shfl_xor_sync(0xffffffffu, part, o);
        if (tid == 0) out[pairI] = part + bvec[0];
    }
}

// ---------------------------------------------------------------------------
// Launch. Inputs (metadata order): posdoc, negdoc, query, query_idf, emb,
// mus, sigmas, W, b. Output: [B,2] float.
// ---------------------------------------------------------------------------
extern "C" void kernel_launch(void* const* d_in, const int* in_sizes, int n_in,
                              void* d_out, int out_size) {
    const int*   posdoc = (const int*)d_in[0];
    const int*   negdoc = (const int*)d_in[1];
    const int*   query  = (const int*)d_in[2];
    // d_in[3] = query_idf (unused by the reference computation)
    const float* emb    = (const float*)d_in[4];
    const float* mus    = (const float*)d_in[5];
    const float* sigmas = (const float*)d_in[6];
    const float* W      = (const float*)d_in[7];
    const float* bvec   = (const float*)d_in[8];
    float* out = (float*)d_out;

    // Unconditional (no static guards per harness rules); not stream ops, not
    // captured into the graph, and the attributes are sticky.
    cudaFuncSetAttribute(knrm_main_kernel,
                         cudaFuncAttributeMaxDynamicSharedMemorySize, SMEM_BYTES);
    cudaFuncSetAttribute(knrm_main_kernel,
                         cudaFuncAttributePreferredSharedMemoryCarveout, 100);

    normalize_emb_kernel<<<(VSZ + 7) / 8, 256>>>(emb);
    knrm_main_kernel<<<BB * 2 * NSPLIT, 256, SMEM_BYTES>>>(
        posdoc, negdoc, query, mus, sigmas, W, bvec, out);
}